// round 9
// baseline (speedup 1.0000x reference)
#include <cuda_runtime.h>

#define NN       50000
#define DIM      512
#define KMAX     32
#define NTHREADS 128
#define SENT     0x7FC00DADu   // NaN payload sentinel: unreachable by finite math

// Score chain: packed word per node  [63:32]=float eknew bits, [31:0]=ready flag.
__device__ unsigned long long g_score[NN];
__device__ float g_eq[NN];    // feats[i].wq_w + wq_b
__device__ float g_ek0[NN];   // feats[i].wk_w + wk_b

__device__ __forceinline__ unsigned long long ld_relaxed_u64(const unsigned long long* p) {
    unsigned long long v;
    asm volatile("ld.global.relaxed.gpu.b64 %0, [%1];" : "=l"(v) : "l"(p) : "memory");
    return v;
}
__device__ __forceinline__ void st_relaxed_u64(unsigned long long* p, unsigned long long v) {
    asm volatile("st.global.relaxed.gpu.b64 [%0], %1;" :: "l"(p), "l"(v) : "memory");
}
__device__ __forceinline__ float ld_relaxed_f32(const float* p) {
    float v;
    asm volatile("ld.global.relaxed.gpu.f32 %0, [%1];" : "=f"(v) : "l"(p) : "memory");
    return v;
}
__device__ __forceinline__ float ld_acquire_f32(const float* p) {
    float v;
    asm volatile("ld.global.acquire.gpu.f32 %0, [%1];" : "=f"(v) : "l"(p) : "memory");
    return v;
}
__device__ __forceinline__ void st_relaxed_f32(float* p, float v) {
    asm volatile("st.global.relaxed.gpu.f32 [%0], %1;" :: "l"(p), "f"(v) : "memory");
}
__device__ __forceinline__ void st_release_f32(float* p, float v) {
    asm volatile("st.global.release.gpu.f32 [%0], %1;" :: "l"(p), "f"(v) : "memory");
}

// One warp per row: eq/ek0 GEMV; reset score flags; sentinel-fill out's word-3 quarter.
__global__ void pre_kernel(const float* __restrict__ feats,
                           const float* __restrict__ wq_w,
                           const float* __restrict__ wq_b,
                           const float* __restrict__ wk_w,
                           const float* __restrict__ wk_b,
                           float*       out)
{
    int gtid = blockIdx.x * blockDim.x + threadIdx.x;
    if (gtid < NN) g_score[gtid] = 0ull;

    // Sentinel-fill ONLY the guarded quarter [384,512) of each row:
    // NN*32 float4 = exactly one per thread at this grid size.
    {
        const unsigned s = SENT;
        float4 sv = make_float4(__uint_as_float(s), __uint_as_float(s),
                                __uint_as_float(s), __uint_as_float(s));
        int row = gtid >> 5;
        int q   = gtid & 31;
        if (row < NN)
            *(float4*)(out + (size_t)row * DIM + 384 + q * 4) = sv;
    }

    int row_i = gtid >> 5;
    int lane  = gtid & 31;
    if (row_i >= NN) return;

    const float4* row = (const float4*)(feats + (size_t)row_i * DIM);
    const float4* q4  = (const float4*)wq_w;
    const float4* k4  = (const float4*)wk_w;
    float sq = 0.f, sk = 0.f;
    #pragma unroll
    for (int j = lane; j < DIM / 4; j += 32) {
        float4 f = row[j];
        float4 q = q4[j];
        float4 k = k4[j];
        sq += f.x*q.x + f.y*q.y + f.z*q.z + f.w*q.w;
        sk += f.x*k.x + f.y*k.y + f.z*k.z + f.w*k.w;
    }
    #pragma unroll
    for (int o = 16; o > 0; o >>= 1) {
        sq += __shfl_down_sync(0xffffffffu, sq, o);
        sk += __shfl_down_sync(0xffffffffu, sk, o);
    }
    if (lane == 0) {
        g_eq[row_i]  = sq + *wq_b;
        g_ek0[row_i] = sk + *wk_b;
    }
}

__global__ void __launch_bounds__(NTHREADS, 12)
attn_kernel(const float* __restrict__ feats,
            const int*   __restrict__ neighbors,
            const int*   __restrict__ deg,
            const float* __restrict__ wk_b,
            float*       out)
{
    __shared__ float        s_a[KMAX];          // early rows [0,nE), late [nE,nV)
    __shared__ const float* s_p[KMAX];
    __shared__ int          s_cnt;

    const int i   = blockIdx.x;
    const int tid = threadIdx.x;
    const int d   = deg[i];

    // ---- prefetch center row (independent of all waits) ----
    const float* fi = feats + (size_t)i * DIM;
    float acc0 = __ldg(fi + tid);
    float acc1 = __ldg(fi + tid + 128);
    float acc2 = __ldg(fi + tid + 256);
    float acc3 = __ldg(fi + tid + 384);

    if (tid < 32) {
        const bool valid = tid < d;
        int   nb    = 0;
        bool  early = false;
        float ej    = 0.f;
        if (valid) {
            nb    = neighbors[i * KMAX + tid];
            early = nb < i;
            if (early) {
                unsigned long long w;
                int it = 0;
                while ((unsigned)((w = ld_relaxed_u64(&g_score[nb]))) == 0u) {
                    if (++it > 8) __nanosleep(20);
                }
                ej = __uint_as_float((unsigned)(w >> 32));
            } else {
                ej = __ldg(&g_ek0[nb]);
            }
        }

        // ---- softmax (no max-subtract: scores O(1), fp32-safe, identical math) ----
        const float wkb = *wk_b;
        const float ei  = __ldg(&g_eq[i]);
        float ex  = valid ? __expf(ei * ej) : 0.f;
        float s   = ex;
        float num = ex * (ej - wkb);
        #pragma unroll
        for (int o = 16; o > 0; o >>= 1) {
            s   += __shfl_xor_sync(0xffffffffu, s, o);
            num += __shfl_xor_sync(0xffffffffu, num, o);
        }

        // ---- publish score IMMEDIATELY (before any row work) ----
        if (tid == 0) {
            float ekn = __ldg(&g_ek0[i]) + ((d > 0) ? num / s : 0.f);
            unsigned long long w =
                ((unsigned long long)__float_as_uint(ekn) << 32) | 1ull;
            st_relaxed_u64(&g_score[i], w);
        }

        // ---- compact: early rows first, then late ----
        unsigned vm = __ballot_sync(0xffffffffu, valid);
        unsigned em = __ballot_sync(0xffffffffu, valid && early);
        unsigned lm = vm & ~em;
        int nE_tot  = __popc(em);
        if (valid) {
            float a = ex / s;
            const float* p = (early ? out : feats) + (size_t)nb * DIM;
            unsigned below = (1u << tid) - 1u;
            int k = early ? __popc(em & below) : nE_tot + __popc(lm & below);
            s_a[k] = a;
            s_p[k] = p;
        }
        if (tid == 0) s_cnt = nE_tot | (__popc(vm) << 16);
    }
    __syncthreads();

    const int nE = s_cnt & 0xffff;
    const int nV = s_cnt >> 16;

    // ---- late rows: original feats, full MLP through L1 ----
    #pragma unroll 4
    for (int k = nE; k < nV; k++) {
        const float  a = s_a[k];
        const float* r = s_p[k];
        acc0 = fmaf(a, __ldg(r + tid),       acc0);
        acc1 = fmaf(a, __ldg(r + tid + 128), acc1);
        acc2 = fmaf(a, __ldg(r + tid + 256), acc2);
        acc3 = fmaf(a, __ldg(r + tid + 384), acc3);
    }

    // ---- early rows: acquire-poll word3; words 0-2 ride the release/acquire pair ----
    unsigned bad = 0;
    for (int k0 = 0; k0 < nE; k0 += 4) {
        float w3[4];
        #pragma unroll
        for (int r = 0; r < 4; r++)
            if (k0 + r < nE) w3[r] = ld_acquire_f32(s_p[k0 + r] + tid + 384);
        #pragma unroll
        for (int r = 0; r < 4; r++) {
            int k = k0 + r;
            if (k < nE) {
                if (__float_as_uint(w3[r]) == SENT) {
                    bad |= 1u << k;
                } else {
                    const float  a = s_a[k];
                    const float* p = s_p[k];
                    acc0 = fmaf(a, ld_relaxed_f32(p + tid),       acc0);
                    acc1 = fmaf(a, ld_relaxed_f32(p + tid + 128), acc1);
                    acc2 = fmaf(a, ld_relaxed_f32(p + tid + 256), acc2);
                    acc3 = fmaf(a, w3[r],                         acc3);
                }
            }
        }
    }
    while (bad) {
        int k = __ffs(bad) - 1;
        bad &= bad - 1;
        const float  a = s_a[k];
        const float* p = s_p[k];
        float v3 = ld_acquire_f32(p + tid + 384);
        while (__float_as_uint(v3) == SENT) {
            __nanosleep(20);
            v3 = ld_acquire_f32(p + tid + 384);
        }
        acc0 = fmaf(a, ld_relaxed_f32(p + tid),       acc0);
        acc1 = fmaf(a, ld_relaxed_f32(p + tid + 128), acc1);
        acc2 = fmaf(a, ld_relaxed_f32(p + tid + 256), acc2);
        acc3 = fmaf(a, v3,                            acc3);
    }

    // ---- publish row: words 0-2 relaxed, word 3 release (orders the others) ----
    float* oi = out + (size_t)i * DIM;
    st_relaxed_f32(oi + tid,       acc0);
    st_relaxed_f32(oi + tid + 128, acc1);
    st_relaxed_f32(oi + tid + 256, acc2);
    st_release_f32(oi + tid + 384, acc3);
}

extern "C" void kernel_launch(void* const* d_in, const int* in_sizes, int n_in,
                              void* d_out, int out_size) {
    const float* feats     = (const float*)d_in[0];
    const float* wq_w      = (const float*)d_in[1];
    const float* wq_b      = (const float*)d_in[2];
    const float* wk_w      = (const float*)d_in[3];
    const float* wk_b      = (const float*)d_in[4];
    const int*   neighbors = (const int*)d_in[5];
    const int*   deg       = (const int*)d_in[6];
    float*       out       = (float*)d_out;

    pre_kernel<<<(NN * 32) / 256, 256>>>(feats, wq_w, wq_b, wk_w, wk_b, out);
    attn_kernel<<<NN, NTHREADS>>>(feats, neighbors, deg, wk_b, out);
}

// round 10
// speedup vs baseline: 1.1573x; 1.1573x over previous
#include <cuda_runtime.h>

#define NN       50000
#define DIM      512
#define KMAX     32
#define NTHREADS 256
#define SENT     0x7FC00DADu   // NaN-payload sentinel: finite math can never produce it

// Score chain: packed word per node  [63:32]=float eknew bits, [31:0]=ready flag.
__device__ unsigned long long g_score[NN];
__device__ float g_eq[NN];    // feats[i].wq_w + wq_b
__device__ float g_ek0[NN];   // feats[i].wk_w + wk_b

__device__ __forceinline__ unsigned long long ld_relaxed_u64(const unsigned long long* p) {
    unsigned long long v;
    asm volatile("ld.global.relaxed.gpu.b64 %0, [%1];" : "=l"(v) : "l"(p) : "memory");
    return v;
}
__device__ __forceinline__ void st_relaxed_u64(unsigned long long* p, unsigned long long v) {
    asm volatile("st.global.relaxed.gpu.b64 [%0], %1;" :: "l"(p), "l"(v) : "memory");
}
__device__ __forceinline__ float ld_relaxed_f32(const float* p) {
    float v;
    asm volatile("ld.global.relaxed.gpu.f32 %0, [%1];" : "=f"(v) : "l"(p) : "memory");
    return v;
}
__device__ __forceinline__ void st_relaxed_f32(float* p, float v) {
    asm volatile("st.global.relaxed.gpu.f32 [%0], %1;" :: "l"(p), "f"(v) : "memory");
}

// One warp per row: eq/ek0 GEMV; reset score flags; sentinel-fill ALL of out.
__global__ void pre_kernel(const float* __restrict__ feats,
                           const float* __restrict__ wq_w,
                           const float* __restrict__ wq_b,
                           const float* __restrict__ wk_w,
                           const float* __restrict__ wk_b,
                           float*       out)
{
    int gtid = blockIdx.x * blockDim.x + threadIdx.x;
    if (gtid < NN) g_score[gtid] = 0ull;

    // Sentinel-fill the whole out buffer (every word is its own readiness flag).
    {
        const unsigned s = SENT;
        float4 sv = make_float4(__uint_as_float(s), __uint_as_float(s),
                                __uint_as_float(s), __uint_as_float(s));
        float4* o4 = (float4*)out;
        const int total4 = NN * DIM / 4;          // 6.4M
        const int nthr   = (NN * 32);             // 1.6M threads
        for (int j = gtid; j < total4; j += nthr) o4[j] = sv;
    }

    int row_i = gtid >> 5;
    int lane  = gtid & 31;
    if (row_i >= NN) return;

    const float4* row = (const float4*)(feats + (size_t)row_i * DIM);
    const float4* q4  = (const float4*)wq_w;
    const float4* k4  = (const float4*)wk_w;
    float sq = 0.f, sk = 0.f;
    #pragma unroll
    for (int j = lane; j < DIM / 4; j += 32) {
        float4 f = row[j];
        float4 q = q4[j];
        float4 k = k4[j];
        sq += f.x*q.x + f.y*q.y + f.z*q.z + f.w*q.w;
        sk += f.x*k.x + f.y*k.y + f.z*k.z + f.w*k.w;
    }
    #pragma unroll
    for (int o = 16; o > 0; o >>= 1) {
        sq += __shfl_down_sync(0xffffffffu, sq, o);
        sk += __shfl_down_sync(0xffffffffu, sk, o);
    }
    if (lane == 0) {
        g_eq[row_i]  = sq + *wq_b;
        g_ek0[row_i] = sk + *wk_b;
    }
}

__global__ void __launch_bounds__(NTHREADS, 6)
attn_kernel(const float* __restrict__ feats,
            const int*   __restrict__ neighbors,
            const int*   __restrict__ deg,
            const float* __restrict__ wk_b,
            float*       out)
{
    __shared__ float        s_a[KMAX];          // early rows [0,nE), late [nE,nV)
    __shared__ const float* s_p[KMAX];
    __shared__ int          s_cnt;

    const int i   = blockIdx.x;
    const int tid = threadIdx.x;
    const int d   = deg[i];

    // ---- prefetch center row (independent of all waits); 2 words/thread ----
    const float* fi = feats + (size_t)i * DIM;
    float acc0 = __ldg(fi + tid);
    float acc1 = __ldg(fi + tid + 256);

    if (tid < 32) {
        const bool valid = tid < d;
        int   nb    = 0;
        bool  early = false;
        float ej    = 0.f;
        if (valid) {
            nb    = neighbors[i * KMAX + tid];
            early = nb < i;
            if (early) {
                // score-chain wait: payload packed in the flag word
                unsigned long long w;
                int it = 0;
                while ((unsigned)((w = ld_relaxed_u64(&g_score[nb]))) == 0u) {
                    if (++it > 8) __nanosleep(20);
                }
                ej = __uint_as_float((unsigned)(w >> 32));
            } else {
                ej = __ldg(&g_ek0[nb]);
            }
        }

        // ---- softmax (no max-subtract: scores O(1), identical math in fp32) ----
        const float wkb = *wk_b;
        const float ei  = __ldg(&g_eq[i]);
        float ex  = valid ? __expf(ei * ej) : 0.f;
        float s   = ex;
        float num = ex * (ej - wkb);
        #pragma unroll
        for (int o = 16; o > 0; o >>= 1) {
            s   += __shfl_xor_sync(0xffffffffu, s, o);
            num += __shfl_xor_sync(0xffffffffu, num, o);
        }

        // ---- publish score IMMEDIATELY (before any row work) ----
        if (tid == 0) {
            float ekn = __ldg(&g_ek0[i]) + ((d > 0) ? num / s : 0.f);
            unsigned long long w =
                ((unsigned long long)__float_as_uint(ekn) << 32) | 1ull;
            st_relaxed_u64(&g_score[i], w);
        }

        // ---- compact: early rows first, then late ----
        unsigned vm = __ballot_sync(0xffffffffu, valid);
        unsigned em = __ballot_sync(0xffffffffu, valid && early);
        unsigned lm = vm & ~em;
        int nE_tot  = __popc(em);
        if (valid) {
            float a = ex / s;
            const float* p = (early ? out : feats) + (size_t)nb * DIM;
            unsigned below = (1u << tid) - 1u;
            int k = early ? __popc(em & below) : nE_tot + __popc(lm & below);
            s_a[k] = a;
            s_p[k] = p;
        }
        if (tid == 0) s_cnt = nE_tot | (__popc(vm) << 16);
    }
    __syncthreads();

    const int nE = s_cnt & 0xffff;
    const int nV = s_cnt >> 16;

    // ---- late rows first (guaranteed ready; gives producers time) ----
    #pragma unroll 4
    for (int k = nE; k < nV; k++) {
        const float  a = s_a[k];
        const float* r = s_p[k];
        acc0 = fmaf(a, __ldg(r + tid),       acc0);
        acc1 = fmaf(a, __ldg(r + tid + 256), acc1);
    }

    // ---- early rows: per-word sentinel check, full MLP, straggler masks ----
    unsigned bad0 = 0, bad1 = 0;
    for (int k0 = 0; k0 < nE; k0 += 4) {
        float w0[4], w1[4];
        #pragma unroll
        for (int r = 0; r < 4; r++) {
            int k = k0 + r;
            if (k < nE) {
                w0[r] = ld_relaxed_f32(s_p[k] + tid);
                w1[r] = ld_relaxed_f32(s_p[k] + tid + 256);
            }
        }
        #pragma unroll
        for (int r = 0; r < 4; r++) {
            int k = k0 + r;
            if (k < nE) {
                const float a = s_a[k];
                if (__float_as_uint(w0[r]) != SENT) acc0 = fmaf(a, w0[r], acc0);
                else                                bad0 |= 1u << k;
                if (__float_as_uint(w1[r]) != SENT) acc1 = fmaf(a, w1[r], acc1);
                else                                bad1 |= 1u << k;
            }
        }
    }
    // retry ONLY straggler words
    while (bad0 | bad1) {
        unsigned m = bad0;
        while (m) {
            int k = __ffs(m) - 1; m &= m - 1;
            float v = ld_relaxed_f32(s_p[k] + tid);
            if (__float_as_uint(v) != SENT) { acc0 = fmaf(s_a[k], v, acc0); bad0 &= ~(1u << k); }
        }
        m = bad1;
        while (m) {
            int k = __ffs(m) - 1; m &= m - 1;
            float v = ld_relaxed_f32(s_p[k] + tid + 256);
            if (__float_as_uint(v) != SENT) { acc1 = fmaf(s_a[k], v, acc1); bad1 &= ~(1u << k); }
        }
        if (bad0 | bad1) __nanosleep(30);
    }

    // ---- publish row: plain relaxed stores; every word carries its own flag ----
    float* oi = out + (size_t)i * DIM;
    st_relaxed_f32(oi + tid,       acc0);
    st_relaxed_f32(oi + tid + 256, acc1);
}

extern "C" void kernel_launch(void* const* d_in, const int* in_sizes, int n_in,
                              void* d_out, int out_size) {
    const float* feats     = (const float*)d_in[0];
    const float* wq_w      = (const float*)d_in[1];
    const float* wq_b      = (const float*)d_in[2];
    const float* wk_w      = (const float*)d_in[3];
    const float* wk_b      = (const float*)d_in[4];
    const int*   neighbors = (const int*)d_in[5];
    const int*   deg       = (const int*)d_in[6];
    float*       out       = (float*)d_out;

    pre_kernel<<<(NN * 32) / 256, 256>>>(feats, wq_w, wq_b, wk_w, wk_b, out);
    attn_kernel<<<NN, NTHREADS>>>(feats, neighbors, deg, wk_b, out);
}

// round 11
// speedup vs baseline: 1.5355x; 1.3268x over previous
#include <cuda_runtime.h>

#define NN       50000
#define DIM      512
#define KMAX     32
#define NTHREADS 128
#define SENT     0x7FC00DADu   // NaN-payload sentinel: finite math can never produce it

// Score chain: packed word per node  [63:32]=float eknew bits, [31:0]=ready flag.
__device__ unsigned long long g_score[NN];
__device__ float g_eq[NN];    // feats[i].wq_w + wq_b
__device__ float g_ek0[NN];   // feats[i].wk_w + wk_b

__device__ __forceinline__ unsigned long long ld_relaxed_u64(const unsigned long long* p) {
    unsigned long long v;
    asm volatile("ld.global.relaxed.gpu.b64 %0, [%1];" : "=l"(v) : "l"(p) : "memory");
    return v;
}
__device__ __forceinline__ void st_relaxed_u64(unsigned long long* p, unsigned long long v) {
    asm volatile("st.global.relaxed.gpu.b64 [%0], %1;" :: "l"(p), "l"(v) : "memory");
}
__device__ __forceinline__ float4 ld_relaxed_v4(const float* p) {
    float4 v;
    asm volatile("ld.global.relaxed.gpu.v4.f32 {%0,%1,%2,%3}, [%4];"
                 : "=f"(v.x), "=f"(v.y), "=f"(v.z), "=f"(v.w) : "l"(p) : "memory");
    return v;
}
__device__ __forceinline__ void st_relaxed_v4(float* p, float4 v) {
    asm volatile("st.global.relaxed.gpu.v4.f32 [%0], {%1,%2,%3,%4};"
                 :: "l"(p), "f"(v.x), "f"(v.y), "f"(v.z), "f"(v.w) : "memory");
}

// One warp per row: eq/ek0 GEMV; reset score flags; sentinel-fill ALL of out.
__global__ void pre_kernel(const float* __restrict__ feats,
                           const float* __restrict__ wq_w,
                           const float* __restrict__ wq_b,
                           const float* __restrict__ wk_w,
                           const float* __restrict__ wk_b,
                           float*       out)
{
    int gtid = blockIdx.x * blockDim.x + threadIdx.x;
    if (gtid < NN) g_score[gtid] = 0ull;

    // Sentinel-fill the whole out buffer (every word is its own readiness flag).
    {
        const unsigned s = SENT;
        float4 sv = make_float4(__uint_as_float(s), __uint_as_float(s),
                                __uint_as_float(s), __uint_as_float(s));
        float4* o4 = (float4*)out;
        const int total4 = NN * DIM / 4;          // 6.4M
        const int nthr   = (NN * 32);             // 1.6M threads
        for (int j = gtid; j < total4; j += nthr) o4[j] = sv;
    }

    int row_i = gtid >> 5;
    int lane  = gtid & 31;
    if (row_i >= NN) return;

    const float4* row = (const float4*)(feats + (size_t)row_i * DIM);
    const float4* q4  = (const float4*)wq_w;
    const float4* k4  = (const float4*)wk_w;
    float sq = 0.f, sk = 0.f;
    #pragma unroll
    for (int j = lane; j < DIM / 4; j += 32) {
        float4 f = row[j];
        float4 q = q4[j];
        float4 k = k4[j];
        sq += f.x*q.x + f.y*q.y + f.z*q.z + f.w*q.w;
        sk += f.x*k.x + f.y*k.y + f.z*k.z + f.w*k.w;
    }
    #pragma unroll
    for (int o = 16; o > 0; o >>= 1) {
        sq += __shfl_down_sync(0xffffffffu, sq, o);
        sk += __shfl_down_sync(0xffffffffu, sk, o);
    }
    if (lane == 0) {
        g_eq[row_i]  = sq + *wq_b;
        g_ek0[row_i] = sk + *wk_b;
    }
}

__global__ void __launch_bounds__(NTHREADS, 12)
attn_kernel(const float* __restrict__ feats,
            const int*   __restrict__ neighbors,
            const int*   __restrict__ deg,
            const float* __restrict__ wk_b,
            float*       out)
{
    __shared__ float        s_a[KMAX];          // early rows [0,nE), late [nE,nV)
    __shared__ const float* s_p[KMAX];
    __shared__ int          s_cnt;

    const int i    = blockIdx.x;
    const int tid  = threadIdx.x;
    const int base = tid * 4;                   // each thread owns 4 contiguous floats
    const int d    = deg[i];

    // ---- prefetch center row (independent of all waits) ----
    const float* fi = feats + (size_t)i * DIM;
    float4 acc = __ldg((const float4*)fi + tid);

    if (tid < 32) {
        const bool valid = tid < d;
        int   nb    = 0;
        bool  early = false;
        float ej    = 0.f;
        if (valid) {
            nb    = neighbors[i * KMAX + tid];
            early = nb < i;
            if (early) {
                // score-chain wait: payload packed in the flag word; hot spin
                unsigned long long w;
                int it = 0;
                while ((unsigned)((w = ld_relaxed_u64(&g_score[nb]))) == 0u) {
                    if (++it > 64) __nanosleep(20);
                }
                ej = __uint_as_float((unsigned)(w >> 32));
            } else {
                ej = __ldg(&g_ek0[nb]);
            }
        }

        // ---- softmax (no max-subtract: scores O(1), identical math in fp32) ----
        const float wkb = *wk_b;
        const float ei  = __ldg(&g_eq[i]);
        float ex  = valid ? __expf(ei * ej) : 0.f;
        float s   = ex;
        float num = ex * (ej - wkb);
        #pragma unroll
        for (int o = 16; o > 0; o >>= 1) {
            s   += __shfl_xor_sync(0xffffffffu, s, o);
            num += __shfl_xor_sync(0xffffffffu, num, o);
        }

        // ---- publish score IMMEDIATELY (before any row work) ----
        if (tid == 0) {
            float ekn = __ldg(&g_ek0[i]) + ((d > 0) ? num / s : 0.f);
            unsigned long long w =
                ((unsigned long long)__float_as_uint(ekn) << 32) | 1ull;
            st_relaxed_u64(&g_score[i], w);
        }

        // ---- compact: early rows first, then late ----
        unsigned vm = __ballot_sync(0xffffffffu, valid);
        unsigned em = __ballot_sync(0xffffffffu, valid && early);
        unsigned lm = vm & ~em;
        int nE_tot  = __popc(em);
        if (valid) {
            float a = ex / s;
            const float* p = (early ? out : feats) + (size_t)nb * DIM;
            unsigned below = (1u << tid) - 1u;
            int k = early ? __popc(em & below) : nE_tot + __popc(lm & below);
            s_a[k] = a;
            s_p[k] = p;
        }
        if (tid == 0) s_cnt = nE_tot | (__popc(vm) << 16);
    }
    __syncthreads();

    const int nE = s_cnt & 0xffff;
    const int nV = s_cnt >> 16;

    // ---- late rows first (guaranteed ready; gives producers time) ----
    #pragma unroll 4
    for (int k = nE; k < nV; k++) {
        const float  a = s_a[k];
        float4 v = __ldg((const float4*)(s_p[k] + base));
        acc.x = fmaf(a, v.x, acc.x);
        acc.y = fmaf(a, v.y, acc.y);
        acc.z = fmaf(a, v.z, acc.z);
        acc.w = fmaf(a, v.w, acc.w);
    }

    // ---- early rows: one relaxed v4 per row, all-lane sentinel check ----
    unsigned bad = 0;
    {
        int k = 0;
        for (; k + 1 < nE; k += 2) {
            float4 va = ld_relaxed_v4(s_p[k]     + base);
            float4 vb = ld_relaxed_v4(s_p[k + 1] + base);
            bool ga = (__float_as_uint(va.x) != SENT) & (__float_as_uint(va.y) != SENT) &
                      (__float_as_uint(va.z) != SENT) & (__float_as_uint(va.w) != SENT);
            bool gb = (__float_as_uint(vb.x) != SENT) & (__float_as_uint(vb.y) != SENT) &
                      (__float_as_uint(vb.z) != SENT) & (__float_as_uint(vb.w) != SENT);
            if (ga) {
                float a = s_a[k];
                acc.x = fmaf(a, va.x, acc.x); acc.y = fmaf(a, va.y, acc.y);
                acc.z = fmaf(a, va.z, acc.z); acc.w = fmaf(a, va.w, acc.w);
            } else bad |= 1u << k;
            if (gb) {
                float a = s_a[k + 1];
                acc.x = fmaf(a, vb.x, acc.x); acc.y = fmaf(a, vb.y, acc.y);
                acc.z = fmaf(a, vb.z, acc.z); acc.w = fmaf(a, vb.w, acc.w);
            } else bad |= 1u << (k + 1);
        }
        if (k < nE) {
            float4 v = ld_relaxed_v4(s_p[k] + base);
            bool g = (__float_as_uint(v.x) != SENT) & (__float_as_uint(v.y) != SENT) &
                     (__float_as_uint(v.z) != SENT) & (__float_as_uint(v.w) != SENT);
            if (g) {
                float a = s_a[k];
                acc.x = fmaf(a, v.x, acc.x); acc.y = fmaf(a, v.y, acc.y);
                acc.z = fmaf(a, v.z, acc.z); acc.w = fmaf(a, v.w, acc.w);
            } else bad |= 1u << k;
        }
    }
    // retry ONLY straggler rows
    while (bad) {
        unsigned m = bad;
        while (m) {
            int k = __ffs(m) - 1; m &= m - 1;
            float4 v = ld_relaxed_v4(s_p[k] + base);
            bool g = (__float_as_uint(v.x) != SENT) & (__float_as_uint(v.y) != SENT) &
                     (__float_as_uint(v.z) != SENT) & (__float_as_uint(v.w) != SENT);
            if (g) {
                float a = s_a[k];
                acc.x = fmaf(a, v.x, acc.x); acc.y = fmaf(a, v.y, acc.y);
                acc.z = fmaf(a, v.z, acc.z); acc.w = fmaf(a, v.w, acc.w);
                bad &= ~(1u << k);
            }
        }
        if (bad) __nanosleep(30);
    }

    // ---- publish row: one relaxed v4 store; every word carries its own flag ----
    st_relaxed_v4(out + (size_t)i * DIM + base, acc);
}

extern "C" void kernel_launch(void* const* d_in, const int* in_sizes, int n_in,
                              void* d_out, int out_size) {
    const float* feats     = (const float*)d_in[0];
    const float* wq_w      = (const float*)d_in[1];
    const float* wq_b      = (const float*)d_in[2];
    const float* wk_w      = (const float*)d_in[3];
    const float* wk_b      = (const float*)d_in[4];
    const int*   neighbors = (const int*)d_in[5];
    const int*   deg       = (const int*)d_in[6];
    float*       out       = (float*)d_out;

    pre_kernel<<<(NN * 32) / 256, 256>>>(feats, wq_w, wq_b, wk_w, wk_b, out);
    attn_kernel<<<NN, NTHREADS>>>(feats, neighbors, deg, wk_b, out);
}

// round 12
// speedup vs baseline: 1.7576x; 1.1447x over previous
#include <cuda_runtime.h>

#define NN       50000
#define DIM      512
#define KMAX     32
#define NTHREADS 64
#define SENT     0x7FC00DADu   // NaN-payload sentinel: finite math can never produce it

// Score chain: packed word per node  [63:32]=float eknew bits, [31:0]=ready flag.
__device__ unsigned long long g_score[NN];
__device__ float g_eq[NN];    // feats[i].wq_w + wq_b
__device__ float g_ek0[NN];   // feats[i].wk_w + wk_b

__device__ __forceinline__ unsigned long long ld_relaxed_u64(const unsigned long long* p) {
    unsigned long long v;
    asm volatile("ld.global.relaxed.gpu.b64 %0, [%1];" : "=l"(v) : "l"(p) : "memory");
    return v;
}
__device__ __forceinline__ void st_relaxed_u64(unsigned long long* p, unsigned long long v) {
    asm volatile("st.global.relaxed.gpu.b64 [%0], %1;" :: "l"(p), "l"(v) : "memory");
}
__device__ __forceinline__ float4 ld_relaxed_v4(const float* p) {
    float4 v;
    asm volatile("ld.global.relaxed.gpu.v4.f32 {%0,%1,%2,%3}, [%4];"
                 : "=f"(v.x), "=f"(v.y), "=f"(v.z), "=f"(v.w) : "l"(p) : "memory");
    return v;
}
__device__ __forceinline__ void st_relaxed_v4(float* p, float4 v) {
    asm volatile("st.global.relaxed.gpu.v4.f32 [%0], {%1,%2,%3,%4};"
                 :: "l"(p), "f"(v.x), "f"(v.y), "f"(v.z), "f"(v.w) : "memory");
}
__device__ __forceinline__ bool v4_good(float4 v) {
    return (__float_as_uint(v.x) != SENT) & (__float_as_uint(v.y) != SENT) &
           (__float_as_uint(v.z) != SENT) & (__float_as_uint(v.w) != SENT);
}
__device__ __forceinline__ void v4_fma(float4& acc, float a, float4 v) {
    acc.x = fmaf(a, v.x, acc.x); acc.y = fmaf(a, v.y, acc.y);
    acc.z = fmaf(a, v.z, acc.z); acc.w = fmaf(a, v.w, acc.w);
}

// One warp per row: eq/ek0 GEMV; reset score flags; sentinel-fill ALL of out.
__global__ void pre_kernel(const float* __restrict__ feats,
                           const float* __restrict__ wq_w,
                           const float* __restrict__ wq_b,
                           const float* __restrict__ wk_w,
                           const float* __restrict__ wk_b,
                           float*       out)
{
    int gtid = blockIdx.x * blockDim.x + threadIdx.x;
    if (gtid < NN) g_score[gtid] = 0ull;

    // Sentinel-fill the whole out buffer (every word is its own readiness flag).
    {
        const unsigned s = SENT;
        float4 sv = make_float4(__uint_as_float(s), __uint_as_float(s),
                                __uint_as_float(s), __uint_as_float(s));
        float4* o4 = (float4*)out;
        const int total4 = NN * DIM / 4;          // 6.4M
        const int nthr   = (NN * 32);             // 1.6M threads
        for (int j = gtid; j < total4; j += nthr) o4[j] = sv;
    }

    int row_i = gtid >> 5;
    int lane  = gtid & 31;
    if (row_i >= NN) return;

    const float4* row = (const float4*)(feats + (size_t)row_i * DIM);
    const float4* q4  = (const float4*)wq_w;
    const float4* k4  = (const float4*)wk_w;
    float sq = 0.f, sk = 0.f;
    #pragma unroll
    for (int j = lane; j < DIM / 4; j += 32) {
        float4 f = row[j];
        float4 q = q4[j];
        float4 k = k4[j];
        sq += f.x*q.x + f.y*q.y + f.z*q.z + f.w*q.w;
        sk += f.x*k.x + f.y*k.y + f.z*k.z + f.w*k.w;
    }
    #pragma unroll
    for (int o = 16; o > 0; o >>= 1) {
        sq += __shfl_down_sync(0xffffffffu, sq, o);
        sk += __shfl_down_sync(0xffffffffu, sk, o);
    }
    if (lane == 0) {
        g_eq[row_i]  = sq + *wq_b;
        g_ek0[row_i] = sk + *wk_b;
    }
}

__global__ void __launch_bounds__(NTHREADS, 24)
attn_kernel(const float* __restrict__ feats,
            const int*   __restrict__ neighbors,
            const int*   __restrict__ deg,
            const float* __restrict__ wk_b,
            float*       out)
{
    __shared__ float        s_a[KMAX];          // early rows [0,nE), late [nE,nV)
    __shared__ const float* s_p[KMAX];
    __shared__ int          s_cnt;

    const int i    = blockIdx.x;
    const int tid  = threadIdx.x;
    const int b0   = tid * 4;                   // first owned segment
    const int b1   = tid * 4 + 256;             // second owned segment
    const int d    = deg[i];

    // ---- prefetch center row (independent of all waits) ----
    const float* fi = feats + (size_t)i * DIM;
    float4 accA = __ldg((const float4*)(fi + b0));
    float4 accB = __ldg((const float4*)(fi + b1));

    if (tid < 32) {
        const bool valid = tid < d;
        int   nb    = 0;
        bool  early = false;
        float ej    = 0.f;
        if (valid) {
            nb    = neighbors[i * KMAX + tid];
            early = nb < i;
            if (early) {
                // score-chain wait: payload packed in the flag word; hot spin
                unsigned long long w;
                int it = 0;
                while ((unsigned)((w = ld_relaxed_u64(&g_score[nb]))) == 0u) {
                    if (++it > 64) __nanosleep(20);
                }
                ej = __uint_as_float((unsigned)(w >> 32));
            } else {
                ej = __ldg(&g_ek0[nb]);
            }
        }

        // ---- softmax (no max-subtract: scores O(1), identical math in fp32) ----
        const float wkb = *wk_b;
        const float ei  = __ldg(&g_eq[i]);
        float ex  = valid ? __expf(ei * ej) : 0.f;
        float s   = ex;
        float num = ex * (ej - wkb);
        #pragma unroll
        for (int o = 16; o > 0; o >>= 1) {
            s   += __shfl_xor_sync(0xffffffffu, s, o);
            num += __shfl_xor_sync(0xffffffffu, num, o);
        }

        // ---- publish score IMMEDIATELY (before any row work) ----
        if (tid == 0) {
            float ekn = __ldg(&g_ek0[i]) + ((d > 0) ? num / s : 0.f);
            unsigned long long w =
                ((unsigned long long)__float_as_uint(ekn) << 32) | 1ull;
            st_relaxed_u64(&g_score[i], w);
        }

        // ---- compact: early rows first, then late ----
        unsigned vm = __ballot_sync(0xffffffffu, valid);
        unsigned em = __ballot_sync(0xffffffffu, valid && early);
        unsigned lm = vm & ~em;
        int nE_tot  = __popc(em);
        if (valid) {
            float a = ex / s;
            const float* p = (early ? out : feats) + (size_t)nb * DIM;
            unsigned below = (1u << tid) - 1u;
            int k = early ? __popc(em & below) : nE_tot + __popc(lm & below);
            s_a[k] = a;
            s_p[k] = p;
        }
        if (tid == 0) s_cnt = nE_tot | (__popc(vm) << 16);
    }
    __syncthreads();

    const int nE = s_cnt & 0xffff;
    const int nV = s_cnt >> 16;

    // ---- late rows first (guaranteed ready; gives producers time) ----
    #pragma unroll 2
    for (int k = nE; k < nV; k++) {
        const float  a = s_a[k];
        const float* r = s_p[k];
        float4 vA = __ldg((const float4*)(r + b0));
        float4 vB = __ldg((const float4*)(r + b1));
        v4_fma(accA, a, vA);
        v4_fma(accB, a, vB);
    }

    // ---- early rows: two relaxed v4 per row, per-segment straggler masks ----
    unsigned badA = 0, badB = 0;
    {
        int k = 0;
        for (; k + 1 < nE; k += 2) {
            const float* p0 = s_p[k];
            const float* p1 = s_p[k + 1];
            float4 a0 = ld_relaxed_v4(p0 + b0);
            float4 a1 = ld_relaxed_v4(p0 + b1);
            float4 c0 = ld_relaxed_v4(p1 + b0);
            float4 c1 = ld_relaxed_v4(p1 + b1);
            float w0 = s_a[k], w1 = s_a[k + 1];
            if (v4_good(a0)) v4_fma(accA, w0, a0); else badA |= 1u << k;
            if (v4_good(a1)) v4_fma(accB, w0, a1); else badB |= 1u << k;
            if (v4_good(c0)) v4_fma(accA, w1, c0); else badA |= 1u << (k + 1);
            if (v4_good(c1)) v4_fma(accB, w1, c1); else badB |= 1u << (k + 1);
        }
        if (k < nE) {
            const float* p0 = s_p[k];
            float4 a0 = ld_relaxed_v4(p0 + b0);
            float4 a1 = ld_relaxed_v4(p0 + b1);
            float w0 = s_a[k];
            if (v4_good(a0)) v4_fma(accA, w0, a0); else badA |= 1u << k;
            if (v4_good(a1)) v4_fma(accB, w0, a1); else badB |= 1u << k;
        }
    }
    // retry ONLY straggler segments
    while (badA | badB) {
        unsigned m = badA;
        while (m) {
            int k = __ffs(m) - 1; m &= m - 1;
            float4 v = ld_relaxed_v4(s_p[k] + b0);
            if (v4_good(v)) { v4_fma(accA, s_a[k], v); badA &= ~(1u << k); }
        }
        m = badB;
        while (m) {
            int k = __ffs(m) - 1; m &= m - 1;
            float4 v = ld_relaxed_v4(s_p[k] + b1);
            if (v4_good(v)) { v4_fma(accB, s_a[k], v); badB &= ~(1u << k); }
        }
        if (badA | badB) __nanosleep(30);
    }

    // ---- publish row: two relaxed v4 stores; every word carries its own flag ----
    float* oi = out + (size_t)i * DIM;
    st_relaxed_v4(oi + b0, accA);
    st_relaxed_v4(oi + b1, accB);
}

extern "C" void kernel_launch(void* const* d_in, const int* in_sizes, int n_in,
                              void* d_out, int out_size) {
    const float* feats     = (const float*)d_in[0];
    const float* wq_w      = (const float*)d_in[1];
    const float* wq_b      = (const float*)d_in[2];
    const float* wk_w      = (const float*)d_in[3];
    const float* wk_b      = (const float*)d_in[4];
    const int*   neighbors = (const int*)d_in[5];
    const int*   deg       = (const int*)d_in[6];
    float*       out       = (float*)d_out;

    pre_kernel<<<(NN * 32) / 256, 256>>>(feats, wq_w, wq_b, wk_w, wk_b, out);
    attn_kernel<<<NN, NTHREADS>>>(feats, neighbors, deg, wk_b, out);
}